// round 2
// baseline (speedup 1.0000x reference)
#include <cuda_runtime.h>
#include <cuda_bf16.h>

#define NN      100000
#define NE      1600000
#define NG      1024
#define EMB_D   32
#define HID_D   64
#define NC      10

// ---------------- scratch (device globals; no allocation allowed) ----------
__device__ float g_x   [NN * EMB_D];   // node input features
__device__ float g_h   [NN * HID_D];   // matmul output (pre-aggregation)
__device__ float g_a   [NN * HID_D];   // layer-1 aggregation / layer-2 input
__device__ float g_b   [NN * HID_D];   // layer-2 aggregation / final node feats
__device__ float g_dis [NN];           // rsqrt(deg)
__device__ float g_deg [NN];
__device__ float g_norm[NE];
__device__ float g_pool[NG * HID_D];
__device__ float g_cnt [NG];

// ---------------- kernels --------------------------------------------------

// zero deg / pool / cnt (runs every replay — keeps launch deterministic)
__global__ void k_zero() {
    int i = blockIdx.x * blockDim.x + threadIdx.x;
    if (i < NN) g_deg[i] = 0.0f;
    if (i < NG * HID_D) g_pool[i] = 0.0f;
    if (i < NG) g_cnt[i] = 0.0f;
}

// deg[dst] += 1
__global__ void k_deg(const int* __restrict__ dst) {
    int e = blockIdx.x * blockDim.x + threadIdx.x;
    if (e < NE) atomicAdd(&g_deg[dst[e]], 1.0f);
}

// dis = rsqrt(1+deg);  x = shape_table[sid] + color_table[cid] (row 0 -> 0)
__global__ void k_embed(const int* __restrict__ sid, const int* __restrict__ cid,
                        const float* __restrict__ stab, const float* __restrict__ ctab) {
    int i = blockIdx.x * blockDim.x + threadIdx.x;
    if (i >= NN) return;
    g_dis[i] = rsqrtf(1.0f + g_deg[i]);
    int s = sid[i], c = cid[i];
    const float4* sr = (const float4*)(stab + s * EMB_D);
    const float4* cr = (const float4*)(ctab + c * EMB_D);
    float4* xr = (float4*)(g_x + i * EMB_D);
#pragma unroll
    for (int k = 0; k < EMB_D / 4; k++) {
        float4 sv = (s == 0) ? make_float4(0, 0, 0, 0) : sr[k];
        float4 cv = (c == 0) ? make_float4(0, 0, 0, 0) : cr[k];
        xr[k] = make_float4(sv.x + cv.x, sv.y + cv.y, sv.z + cv.z, sv.w + cv.w);
    }
}

// norm[e] = dis[src] * dis[dst]
__global__ void k_norm(const int* __restrict__ src, const int* __restrict__ dst) {
    int e = blockIdx.x * blockDim.x + threadIdx.x;
    if (e < NE) g_norm[e] = g_dis[src[e]] * g_dis[dst[e]];
}

// h = x @ W1 [32x64]; seed agg = h * dis^2 (self-loop term)
__global__ void k_mm1(const float* __restrict__ W1) {
    __shared__ float sW[EMB_D * HID_D];
    for (int t = threadIdx.x; t < EMB_D * HID_D; t += blockDim.x) sW[t] = W1[t];
    __syncthreads();
    long total = (long)NN * HID_D;
    for (long idx = blockIdx.x * (long)blockDim.x + threadIdx.x; idx < total;
         idx += (long)gridDim.x * blockDim.x) {
        int i = (int)(idx / HID_D), j = (int)(idx % HID_D);
        const float* xr = g_x + i * EMB_D;
        float s = 0.0f;
#pragma unroll
        for (int k = 0; k < EMB_D; k++) s = fmaf(xr[k], sW[k * HID_D + j], s);
        g_h[idx] = s;
        float d = g_dis[i];
        g_a[idx] = s * d * d;
    }
}

// h = in @ W2 [64x64]; seed out = h * dis^2
__global__ void k_mm2(const float* __restrict__ W2) {
    __shared__ float sW[HID_D * HID_D];
    for (int t = threadIdx.x; t < HID_D * HID_D; t += blockDim.x) sW[t] = W2[t];
    __syncthreads();
    long total = (long)NN * HID_D;
    for (long idx = blockIdx.x * (long)blockDim.x + threadIdx.x; idx < total;
         idx += (long)gridDim.x * blockDim.x) {
        int i = (int)(idx / HID_D), j = (int)(idx % HID_D);
        const float* xr = g_a + i * HID_D;
        float s = 0.0f;
#pragma unroll
        for (int k = 0; k < HID_D; k++) s = fmaf(xr[k], sW[k * HID_D + j], s);
        g_h[idx] = s;
        float d = g_dis[i];
        g_b[idx] = s * d * d;
    }
}

// agg[dst] += h[src] * norm  — device-side global refs (NOT host-passed symbols)
__device__ __forceinline__ void scatter_body(const int* __restrict__ src,
                                             const int* __restrict__ dst,
                                             const float* __restrict__ h,
                                             float* __restrict__ agg) {
    long idx = blockIdx.x * (long)blockDim.x + threadIdx.x;
    long total = (long)NE * (HID_D / 4);
    if (idx >= total) return;
    int e = (int)(idx >> 4);          // HID_D/4 == 16
    int q = (int)(idx & 15);
    int s = src[e], d = dst[e];
    float nr = g_norm[e];
    float4 v = *(const float4*)(h + (long)s * HID_D + q * 4);
    float* out = agg + (long)d * HID_D + q * 4;
    atomicAdd(out + 0, v.x * nr);
    atomicAdd(out + 1, v.y * nr);
    atomicAdd(out + 2, v.z * nr);
    atomicAdd(out + 3, v.w * nr);
}

__global__ void k_scatter1(const int* __restrict__ src, const int* __restrict__ dst) {
    scatter_body(src, dst, g_h, g_a);   // device-side symbol addresses: valid
}
__global__ void k_scatter2(const int* __restrict__ src, const int* __restrict__ dst) {
    scatter_body(src, dst, g_h, g_b);
}

// agg = relu(agg + bias)
__global__ void k_relubias1(const float* __restrict__ bias) {
    long idx = blockIdx.x * (long)blockDim.x + threadIdx.x;
    if (idx >= (long)NN * HID_D) return;
    float v = g_a[idx] + bias[(int)(idx % HID_D)];
    g_a[idx] = v > 0.0f ? v : 0.0f;
}
__global__ void k_relubias2(const float* __restrict__ bias) {
    long idx = blockIdx.x * (long)blockDim.x + threadIdx.x;
    if (idx >= (long)NN * HID_D) return;
    float v = g_b[idx] + bias[(int)(idx % HID_D)];
    g_b[idx] = v > 0.0f ? v : 0.0f;
}

// pooled sums + counts
__global__ void k_pool(const int* __restrict__ batch) {
    long idx = blockIdx.x * (long)blockDim.x + threadIdx.x;
    if (idx >= (long)NN * HID_D) return;
    int i = (int)(idx / HID_D), j = (int)(idx % HID_D);
    int b = batch[i];
    atomicAdd(&g_pool[b * HID_D + j], g_b[idx]);
    if (j == 0) atomicAdd(&g_cnt[b], 1.0f);
}

// out[b,c] = bl[c] + sum_j pool[b,j]/cnt[b] * Wl[j,c]
__global__ void k_final(const float* __restrict__ Wl, const float* __restrict__ bl,
                        float* __restrict__ out) {
    int idx = blockIdx.x * blockDim.x + threadIdx.x;
    if (idx >= NG * NC) return;
    int b = idx / NC, c = idx % NC;
    float cnt = g_cnt[b];
    float inv = 1.0f / fmaxf(cnt, 1.0f);
    float s = bl[c];
#pragma unroll
    for (int j = 0; j < HID_D; j++)
        s = fmaf(g_pool[b * HID_D + j] * inv, Wl[j * NC + c], s);
    out[idx] = s;
}

// ---------------- launch ----------------------------------------------------
extern "C" void kernel_launch(void* const* d_in, const int* in_sizes, int n_in,
                              void* d_out, int out_size) {
    const int*   shape_id = (const int*)  d_in[0];
    const int*   color_id = (const int*)  d_in[1];
    const int*   edge     = (const int*)  d_in[2];   // [2, NE] row-major
    const int*   batch    = (const int*)  d_in[3];
    const float* stab     = (const float*)d_in[4];
    const float* ctab     = (const float*)d_in[5];
    const float* W1       = (const float*)d_in[6];
    const float* b1       = (const float*)d_in[7];
    const float* W2       = (const float*)d_in[8];
    const float* b2       = (const float*)d_in[9];
    const float* Wl       = (const float*)d_in[10];
    const float* bl       = (const float*)d_in[11];
    float*       out      = (float*)d_out;

    const int* src = edge;
    const int* dst = edge + NE;

    const int T = 256;
    auto blk = [](long n, int t) { return (int)((n + t - 1) / t); };

    k_zero<<<blk(NN, T), T>>>();
    k_deg<<<blk(NE, T), T>>>(dst);
    k_embed<<<blk(NN, T), T>>>(shape_id, color_id, stab, ctab);
    k_norm<<<blk(NE, T), T>>>(src, dst);

    // layer 1
    k_mm1<<<blk((long)NN * HID_D, T), T>>>(W1);
    k_scatter1<<<blk((long)NE * 16, T), T>>>(src, dst);
    k_relubias1<<<blk((long)NN * HID_D, T), T>>>(b1);

    // layer 2
    k_mm2<<<blk((long)NN * HID_D, T), T>>>(W2);
    k_scatter2<<<blk((long)NE * 16, T), T>>>(src, dst);
    k_relubias2<<<blk((long)NN * HID_D, T), T>>>(b2);

    // pool + classify
    k_pool<<<blk((long)NN * HID_D, T), T>>>(batch);
    k_final<<<blk(NG * NC, T), T>>>(Wl, bl, out);
}

// round 3
// speedup vs baseline: 2.1681x; 2.1681x over previous
#include <cuda_runtime.h>
#include <cuda_bf16.h>

#define NN      100000
#define NE      1600000
#define NG      1024
#define EMB_D   32
#define HID_D   64
#define NC      10

// ---------------- scratch (device globals) ----------------------------------
__device__ float g_x   [NN * EMB_D];   // node input features
__device__ float g_h   [NN * HID_D];   // hs = (x@W)*dis  (pre-scaled matmul out)
__device__ float g_a   [NN * HID_D];   // accumulator layer1 / input layer2
__device__ float g_b   [NN * HID_D];   // accumulator layer2
__device__ float g_dis [NN];           // rsqrt(1+deg)
__device__ float g_deg [NN];
__device__ float g_pool[NG * HID_D];
__device__ float g_cnt [NG];

__device__ __forceinline__ void red_v4(float* p, float4 v) {
    asm volatile("red.global.add.v4.f32 [%0], {%1,%2,%3,%4};"
                 :: "l"(p), "f"(v.x), "f"(v.y), "f"(v.z), "f"(v.w) : "memory");
}

// ---------------- kernels ----------------------------------------------------

__global__ void k_zero() {
    int i = blockIdx.x * blockDim.x + threadIdx.x;
    if (i < NN) g_deg[i] = 0.0f;
    if (i < NG * HID_D) g_pool[i] = 0.0f;
    if (i < NG) g_cnt[i] = 0.0f;
}

__global__ void k_deg(const int* __restrict__ dst) {
    int e = blockIdx.x * blockDim.x + threadIdx.x;
    if (e < NE) atomicAdd(&g_deg[dst[e]], 1.0f);
}

// dis = rsqrt(1+deg); x = shape_table[sid]+color_table[cid] (row0 -> 0); cnt[batch]++
__global__ void k_embed(const int* __restrict__ sid, const int* __restrict__ cid,
                        const float* __restrict__ stab, const float* __restrict__ ctab,
                        const int* __restrict__ batch) {
    int i = blockIdx.x * blockDim.x + threadIdx.x;
    if (i >= NN) return;
    g_dis[i] = rsqrtf(1.0f + g_deg[i]);
    atomicAdd(&g_cnt[batch[i]], 1.0f);
    int s = sid[i], c = cid[i];
    const float4* sr = (const float4*)(stab + s * EMB_D);
    const float4* cr = (const float4*)(ctab + c * EMB_D);
    float4* xr = (float4*)(g_x + i * EMB_D);
#pragma unroll
    for (int k = 0; k < EMB_D / 4; k++) {
        float4 sv = (s == 0) ? make_float4(0, 0, 0, 0) : sr[k];
        float4 cv = (c == 0) ? make_float4(0, 0, 0, 0) : cr[k];
        xr[k] = make_float4(sv.x + cv.x, sv.y + cv.y, sv.z + cv.z, sv.w + cv.w);
    }
}

// hs = (x @ W1) * dis;  acc seed g_a = hs   (thread: one node x 4 outputs)
__global__ void k_mm1(const float* __restrict__ W1) {
    __shared__ float4 sW[EMB_D * 16];   // [k][j4]
    for (int t = threadIdx.x; t < EMB_D * 16; t += blockDim.x)
        sW[t] = ((const float4*)W1)[t];
    __syncthreads();
    int t = blockIdx.x * blockDim.x + threadIdx.x;
    if (t >= NN * 16) return;
    int i = t >> 4, jq = t & 15;
    const float4* xr = (const float4*)(g_x + i * EMB_D);
    float4 acc = make_float4(0, 0, 0, 0);
#pragma unroll
    for (int k4 = 0; k4 < EMB_D / 4; k4++) {
        float4 xv = xr[k4];
#pragma unroll
        for (int u = 0; u < 4; u++) {
            float xk = (u == 0) ? xv.x : (u == 1) ? xv.y : (u == 2) ? xv.z : xv.w;
            float4 w = sW[(k4 * 4 + u) * 16 + jq];
            acc.x = fmaf(xk, w.x, acc.x);
            acc.y = fmaf(xk, w.y, acc.y);
            acc.z = fmaf(xk, w.z, acc.z);
            acc.w = fmaf(xk, w.w, acc.w);
        }
    }
    float d = g_dis[i];
    float4 hs = make_float4(acc.x * d, acc.y * d, acc.z * d, acc.w * d);
    ((float4*)g_h)[t] = hs;
    ((float4*)g_a)[t] = hs;    // self-loop seed: dis*hs = h*dis^2 after epilogue
}

// hs = (g_a @ W2) * dis;  acc seed g_b = hs
__global__ void k_mm2(const float* __restrict__ W2) {
    __shared__ float4 sW[HID_D * 16];
    for (int t = threadIdx.x; t < HID_D * 16; t += blockDim.x)
        sW[t] = ((const float4*)W2)[t];
    __syncthreads();
    int t = blockIdx.x * blockDim.x + threadIdx.x;
    if (t >= NN * 16) return;
    int i = t >> 4, jq = t & 15;
    const float4* xr = (const float4*)(g_a + i * HID_D);
    float4 acc = make_float4(0, 0, 0, 0);
#pragma unroll
    for (int k4 = 0; k4 < HID_D / 4; k4++) {
        float4 xv = xr[k4];
#pragma unroll
        for (int u = 0; u < 4; u++) {
            float xk = (u == 0) ? xv.x : (u == 1) ? xv.y : (u == 2) ? xv.z : xv.w;
            float4 w = sW[(k4 * 4 + u) * 16 + jq];
            acc.x = fmaf(xk, w.x, acc.x);
            acc.y = fmaf(xk, w.y, acc.y);
            acc.z = fmaf(xk, w.z, acc.z);
            acc.w = fmaf(xk, w.w, acc.w);
        }
    }
    float d = g_dis[i];
    float4 hs = make_float4(acc.x * d, acc.y * d, acc.z * d, acc.w * d);
    ((float4*)g_h)[t] = hs;
    ((float4*)g_b)[t] = hs;
}

// acc[dst] += hs[src]   — 16 threads/edge, one red.v4 each
__device__ __forceinline__ void scatter_body(const int* __restrict__ src,
                                             const int* __restrict__ dst,
                                             const float* __restrict__ hs,
                                             float* __restrict__ acc) {
    long idx = blockIdx.x * (long)blockDim.x + threadIdx.x;
    if (idx >= (long)NE * 16) return;
    int e = (int)(idx >> 4);
    int q = (int)(idx & 15);
    int s = __ldg(src + e), d = __ldg(dst + e);
    float4 v = *(const float4*)(hs + (long)s * HID_D + q * 4);
    red_v4(acc + (long)d * HID_D + q * 4, v);
}

__global__ void k_scatter1(const int* __restrict__ src, const int* __restrict__ dst) {
    scatter_body(src, dst, g_h, g_a);
}
__global__ void k_scatter2(const int* __restrict__ src, const int* __restrict__ dst) {
    scatter_body(src, dst, g_h, g_b);
}

// g_a = relu(dis * acc + b1)   (in place; becomes layer-2 input)
__global__ void k_relubias1(const float* __restrict__ bias) {
    int t = blockIdx.x * blockDim.x + threadIdx.x;
    if (t >= NN * 16) return;
    int i = t >> 4, jq = t & 15;
    float d = g_dis[i];
    float4 v = ((const float4*)g_a)[t];
    float4 b = ((const float4*)bias)[jq];
    v.x = fmaxf(fmaf(d, v.x, b.x), 0.0f);
    v.y = fmaxf(fmaf(d, v.y, b.y), 0.0f);
    v.z = fmaxf(fmaf(d, v.z, b.z), 0.0f);
    v.w = fmaxf(fmaf(d, v.w, b.w), 0.0f);
    ((float4*)g_a)[t] = v;
}

// final node feats = relu(dis * acc2 + b2), reduced straight into pool sums
__global__ void k_relupool(const float* __restrict__ bias, const int* __restrict__ batch) {
    int t = blockIdx.x * blockDim.x + threadIdx.x;
    if (t >= NN * 16) return;
    int i = t >> 4, jq = t & 15;
    float d = g_dis[i];
    int bt = __ldg(batch + i);
    float4 v = ((const float4*)g_b)[t];
    float4 b = ((const float4*)bias)[jq];
    v.x = fmaxf(fmaf(d, v.x, b.x), 0.0f);
    v.y = fmaxf(fmaf(d, v.y, b.y), 0.0f);
    v.z = fmaxf(fmaf(d, v.z, b.z), 0.0f);
    v.w = fmaxf(fmaf(d, v.w, b.w), 0.0f);
    red_v4(g_pool + bt * HID_D + jq * 4, v);
}

// out[b,c] = bl[c] + sum_j pool[b,j]/cnt[b] * Wl[j,c]
__global__ void k_final(const float* __restrict__ Wl, const float* __restrict__ bl,
                        float* __restrict__ out) {
    int idx = blockIdx.x * blockDim.x + threadIdx.x;
    if (idx >= NG * NC) return;
    int b = idx / NC, c = idx % NC;
    float inv = 1.0f / fmaxf(g_cnt[b], 1.0f);
    float s = bl[c];
#pragma unroll
    for (int j = 0; j < HID_D; j++)
        s = fmaf(g_pool[b * HID_D + j] * inv, Wl[j * NC + c], s);
    out[idx] = s;
}

// ---------------- launch ------------------------------------------------------
extern "C" void kernel_launch(void* const* d_in, const int* in_sizes, int n_in,
                              void* d_out, int out_size) {
    const int*   shape_id = (const int*)  d_in[0];
    const int*   color_id = (const int*)  d_in[1];
    const int*   edge     = (const int*)  d_in[2];   // [2, NE]
    const int*   batch    = (const int*)  d_in[3];
    const float* stab     = (const float*)d_in[4];
    const float* ctab     = (const float*)d_in[5];
    const float* W1       = (const float*)d_in[6];
    const float* b1       = (const float*)d_in[7];
    const float* W2       = (const float*)d_in[8];
    const float* b2       = (const float*)d_in[9];
    const float* Wl       = (const float*)d_in[10];
    const float* bl       = (const float*)d_in[11];
    float*       out      = (float*)d_out;

    const int* src = edge;
    const int* dst = edge + NE;

    const int T = 256;
    auto blk = [](long n, int t) { return (int)((n + t - 1) / t); };

    k_zero <<<blk(NN, T), T>>>();
    k_deg  <<<blk(NE, T), T>>>(dst);
    k_embed<<<blk(NN, T), T>>>(shape_id, color_id, stab, ctab, batch);

    // layer 1
    k_mm1      <<<blk((long)NN * 16, T), T>>>(W1);
    k_scatter1 <<<blk((long)NE * 16, T), T>>>(src, dst);
    k_relubias1<<<blk((long)NN * 16, T), T>>>(b1);

    // layer 2
    k_mm2      <<<blk((long)NN * 16, T), T>>>(W2);
    k_scatter2 <<<blk((long)NE * 16, T), T>>>(src, dst);
    k_relupool <<<blk((long)NN * 16, T), T>>>(b2, batch);

    k_final<<<blk(NG * NC, T), T>>>(Wl, bl, out);
}

// round 4
// speedup vs baseline: 3.3882x; 1.5628x over previous
#include <cuda_runtime.h>
#include <cuda_bf16.h>

#define NN      100000
#define NE      1600000
#define NG      1024
#define EMB_D   32
#define HID_D   64
#define NC      10

#define SCAN_B  256
#define NBLK    ((NN + SCAN_B - 1) / SCAN_B)   // 391

// ---------------- scratch (device globals) ----------------------------------
__device__ float g_x   [NN * EMB_D];   // node input features
__device__ float g_h   [NN * HID_D];   // hs = (x@W)*dis
__device__ float g_a   [NN * HID_D];   // layer-1 output / layer-2 input
__device__ float g_dis [NN];
__device__ int   g_ideg[NN];
__device__ int   g_off [NN + 1];       // CSR offsets (exclusive)
__device__ int   g_cur [NN];           // fill cursors
__device__ int   g_bsum[512];          // block sums for scan
__device__ int   g_csrc[NE];           // CSR src-ids grouped by dst
__device__ float g_pool[NG * HID_D];
__device__ float g_cnt [NG];

__device__ __forceinline__ void red_v4(float* p, float4 v) {
    asm volatile("red.global.add.v4.f32 [%0], {%1,%2,%3,%4};"
                 :: "l"(p), "f"(v.x), "f"(v.y), "f"(v.z), "f"(v.w) : "memory");
}
__device__ __forceinline__ float4 f4add(float4 a, float4 b) {
    return make_float4(a.x + b.x, a.y + b.y, a.z + b.z, a.w + b.w);
}

// ---------------- setup kernels ----------------------------------------------

__global__ void k_zero() {
    int i = blockIdx.x * blockDim.x + threadIdx.x;
    if (i < NN) g_ideg[i] = 0;
    if (i < NG * HID_D) g_pool[i] = 0.0f;
    if (i < NG) g_cnt[i] = 0.0f;
}

__global__ void k_deg(const int* __restrict__ dst) {
    int e = blockIdx.x * blockDim.x + threadIdx.x;
    if (e < NE) atomicAdd(&g_ideg[dst[e]], 1);
}

// block-local inclusive scan of degrees; block totals to g_bsum
__global__ void k_scan1() {
    __shared__ int s[SCAN_B];
    int i = blockIdx.x * SCAN_B + threadIdx.x;
    int v = (i < NN) ? g_ideg[i] : 0;
    s[threadIdx.x] = v;
    __syncthreads();
    for (int o = 1; o < SCAN_B; o <<= 1) {
        int t = (threadIdx.x >= o) ? s[threadIdx.x - o] : 0;
        __syncthreads();
        s[threadIdx.x] += t;
        __syncthreads();
    }
    if (i < NN) g_off[i] = s[threadIdx.x];          // block-inclusive (temp)
    if (threadIdx.x == SCAN_B - 1) g_bsum[blockIdx.x] = s[SCAN_B - 1];
}

// exclusive scan of the 391 block sums (single block)
__global__ void k_scan2() {
    __shared__ int s[512];
    int t = threadIdx.x;
    int orig = (t < NBLK) ? g_bsum[t] : 0;
    s[t] = orig;
    __syncthreads();
    for (int o = 1; o < 512; o <<= 1) {
        int v = (t >= o) ? s[t - o] : 0;
        __syncthreads();
        s[t] += v;
        __syncthreads();
    }
    if (t < NBLK) g_bsum[t] = s[t] - orig;          // exclusive
    if (t == 0) g_off[NN] = NE;
}

// exclusive global offsets + cursors
__global__ void k_scan3() {
    int i = blockIdx.x * SCAN_B + threadIdx.x;
    if (i >= NN) return;
    int v = g_off[i] - g_ideg[i] + g_bsum[blockIdx.x];
    g_off[i] = v;
    g_cur[i] = v;
}

// fill CSR: src ids grouped by dst (order within bucket irrelevant)
__global__ void k_fill(const int* __restrict__ src, const int* __restrict__ dst) {
    int e = blockIdx.x * blockDim.x + threadIdx.x;
    if (e >= NE) return;
    int p = atomicAdd(&g_cur[dst[e]], 1);
    g_csrc[p] = src[e];
}

// dis = rsqrt(1+deg); x = shape_table[sid]+color_table[cid] (row0 -> 0); cnt[batch]++
__global__ void k_embed(const int* __restrict__ sid, const int* __restrict__ cid,
                        const float* __restrict__ stab, const float* __restrict__ ctab,
                        const int* __restrict__ batch) {
    int i = blockIdx.x * blockDim.x + threadIdx.x;
    if (i >= NN) return;
    g_dis[i] = rsqrtf(1.0f + (float)g_ideg[i]);
    atomicAdd(&g_cnt[batch[i]], 1.0f);
    int s = sid[i], c = cid[i];
    const float4* sr = (const float4*)(stab + s * EMB_D);
    const float4* cr = (const float4*)(ctab + c * EMB_D);
    float4* xr = (float4*)(g_x + i * EMB_D);
#pragma unroll
    for (int k = 0; k < EMB_D / 4; k++) {
        float4 sv = (s == 0) ? make_float4(0, 0, 0, 0) : sr[k];
        float4 cv = (c == 0) ? make_float4(0, 0, 0, 0) : cr[k];
        xr[k] = f4add(sv, cv);
    }
}

// ---------------- matmuls (smem-tiled: 16 nodes per 256-thread block) --------

// hs = (x @ W1) * dis -> g_h
__global__ void k_mm1(const float* __restrict__ W1) {
    __shared__ float4 sW[EMB_D * 16];          // W1 as [k][j4], 2KB
    __shared__ float  sx[16 * EMB_D];          // 16 node rows, 2KB
    int tid = threadIdx.x;
    int node0 = blockIdx.x * 16;
#pragma unroll
    for (int t = tid; t < EMB_D * 16; t += 256) sW[t] = ((const float4*)W1)[t];
    if (tid < 16 * EMB_D / 4)
        ((float4*)sx)[tid] = ((const float4*)(g_x + (long)node0 * EMB_D))[tid];
    __syncthreads();
    int n = tid >> 4, jq = tid & 15;
    int i = node0 + n;
    float4 acc = make_float4(0, 0, 0, 0);
#pragma unroll
    for (int k = 0; k < EMB_D; k++) {
        float xk = sx[n * EMB_D + k];
        float4 w = sW[k * 16 + jq];
        acc.x = fmaf(xk, w.x, acc.x);
        acc.y = fmaf(xk, w.y, acc.y);
        acc.z = fmaf(xk, w.z, acc.z);
        acc.w = fmaf(xk, w.w, acc.w);
    }
    float d = g_dis[i];
    ((float4*)g_h)[i * 16 + jq] = make_float4(acc.x * d, acc.y * d, acc.z * d, acc.w * d);
}

// hs = (g_a @ W2) * dis -> g_h
__global__ void k_mm2(const float* __restrict__ W2) {
    __shared__ float4 sW[HID_D * 16];          // 4KB
    __shared__ float  sx[16 * HID_D];          // 4KB
    int tid = threadIdx.x;
    int node0 = blockIdx.x * 16;
#pragma unroll
    for (int t = tid; t < HID_D * 16; t += 256) sW[t] = ((const float4*)W2)[t];
    ((float4*)sx)[tid] = ((const float4*)(g_a + (long)node0 * HID_D))[tid];
    __syncthreads();
    int n = tid >> 4, jq = tid & 15;
    int i = node0 + n;
    float4 acc = make_float4(0, 0, 0, 0);
#pragma unroll
    for (int k = 0; k < HID_D; k++) {
        float xk = sx[n * HID_D + k];
        float4 w = sW[k * 16 + jq];
        acc.x = fmaf(xk, w.x, acc.x);
        acc.y = fmaf(xk, w.y, acc.y);
        acc.z = fmaf(xk, w.z, acc.z);
        acc.w = fmaf(xk, w.w, acc.w);
    }
    float d = g_dis[i];
    ((float4*)g_h)[i * 16 + jq] = make_float4(acc.x * d, acc.y * d, acc.z * d, acc.w * d);
}

// ---------------- CSR gather + fused epilogues -------------------------------
// out_i = relu( dis_i * ( sum_{s in in(i)} hs_s + hs_i ) + bias )

__global__ void k_gather1(const float* __restrict__ bias) {
    int t = blockIdx.x * blockDim.x + threadIdx.x;
    if (t >= NN * 16) return;
    int i = t >> 4, jq = t & 15;
    int beg = g_off[i], end = g_off[i + 1];
    float4 acc = ((const float4*)g_h)[i * 16 + jq];           // self-loop seed
    for (int e = beg; e < end; e++) {
        int s = g_csrc[e];
        acc = f4add(acc, ((const float4*)g_h)[s * 16 + jq]);
    }
    float d = g_dis[i];
    float4 b = ((const float4*)bias)[jq];
    float4 v;
    v.x = fmaxf(fmaf(d, acc.x, b.x), 0.0f);
    v.y = fmaxf(fmaf(d, acc.y, b.y), 0.0f);
    v.z = fmaxf(fmaf(d, acc.z, b.z), 0.0f);
    v.w = fmaxf(fmaf(d, acc.w, b.w), 0.0f);
    ((float4*)g_a)[t] = v;
}

// layer 2: same gather, epilogue reduces straight into pool
__global__ void k_gather2(const float* __restrict__ bias, const int* __restrict__ batch) {
    int t = blockIdx.x * blockDim.x + threadIdx.x;
    if (t >= NN * 16) return;
    int i = t >> 4, jq = t & 15;
    int beg = g_off[i], end = g_off[i + 1];
    float4 acc = ((const float4*)g_h)[i * 16 + jq];
    for (int e = beg; e < end; e++) {
        int s = g_csrc[e];
        acc = f4add(acc, ((const float4*)g_h)[s * 16 + jq]);
    }
    float d = g_dis[i];
    float4 b = ((const float4*)bias)[jq];
    float4 v;
    v.x = fmaxf(fmaf(d, acc.x, b.x), 0.0f);
    v.y = fmaxf(fmaf(d, acc.y, b.y), 0.0f);
    v.z = fmaxf(fmaf(d, acc.z, b.z), 0.0f);
    v.w = fmaxf(fmaf(d, acc.w, b.w), 0.0f);
    int bt = __ldg(batch + i);
    red_v4(g_pool + bt * HID_D + jq * 4, v);
}

// out[b,c] = bl[c] + sum_j pool[b,j]/cnt[b] * Wl[j,c]
__global__ void k_final(const float* __restrict__ Wl, const float* __restrict__ bl,
                        float* __restrict__ out) {
    int idx = blockIdx.x * blockDim.x + threadIdx.x;
    if (idx >= NG * NC) return;
    int b = idx / NC, c = idx % NC;
    float inv = 1.0f / fmaxf(g_cnt[b], 1.0f);
    float s = bl[c];
#pragma unroll
    for (int j = 0; j < HID_D; j++)
        s = fmaf(g_pool[b * HID_D + j] * inv, Wl[j * NC + c], s);
    out[idx] = s;
}

// ---------------- launch ------------------------------------------------------
extern "C" void kernel_launch(void* const* d_in, const int* in_sizes, int n_in,
                              void* d_out, int out_size) {
    const int*   shape_id = (const int*)  d_in[0];
    const int*   color_id = (const int*)  d_in[1];
    const int*   edge     = (const int*)  d_in[2];   // [2, NE]
    const int*   batch    = (const int*)  d_in[3];
    const float* stab     = (const float*)d_in[4];
    const float* ctab     = (const float*)d_in[5];
    const float* W1       = (const float*)d_in[6];
    const float* b1       = (const float*)d_in[7];
    const float* W2       = (const float*)d_in[8];
    const float* b2       = (const float*)d_in[9];
    const float* Wl       = (const float*)d_in[10];
    const float* bl       = (const float*)d_in[11];
    float*       out      = (float*)d_out;

    const int* src = edge;
    const int* dst = edge + NE;

    const int T = 256;
    auto blk = [](long n, int t) { return (int)((n + t - 1) / t); };

    // CSR build (once; used by both layers)
    k_zero <<<blk(NN, T), T>>>();
    k_deg  <<<blk(NE, T), T>>>(dst);
    k_scan1<<<NBLK, SCAN_B>>>();
    k_scan2<<<1, 512>>>();
    k_scan3<<<NBLK, SCAN_B>>>();
    k_fill <<<blk(NE, T), T>>>(src, dst);

    k_embed<<<blk(NN, T), T>>>(shape_id, color_id, stab, ctab, batch);

    // layer 1
    k_mm1    <<<NN / 16, T>>>(W1);
    k_gather1<<<blk((long)NN * 16, T), T>>>(b1);

    // layer 2
    k_mm2    <<<NN / 16, T>>>(W2);
    k_gather2<<<blk((long)NN * 16, T), T>>>(b2, batch);

    k_final<<<blk(NG * NC, T), T>>>(Wl, bl, out);
}

// round 5
// speedup vs baseline: 3.8080x; 1.1239x over previous
#include <cuda_runtime.h>
#include <cuda_bf16.h>

#define NN      100000
#define NE      1600000
#define NG      1024
#define EMB_D   32
#define HID_D   64
#define NC      10
#define NSH     17          // N_SHAPE+1
#define NCO     9           // N_COLOR+1

#define SCAN_B  256
#define NBLK    ((NN + SCAN_B - 1) / SCAN_B)   // 391

// ---------------- scratch (device globals) ----------------------------------
__device__ float g_h   [NN * HID_D];   // hs = h*dis (pre-scaled features)
__device__ float g_a   [NN * HID_D];   // layer-1 output / layer-2 input
__device__ float g_dis [NN];
__device__ int   g_ideg[NN];
__device__ int   g_off [NN + 1];       // CSR offsets (exclusive)
__device__ int   g_cur [NN];           // fill cursors
__device__ int   g_bsum[512];          // block sums for scan
__device__ int   g_csrc[NE];           // CSR src-ids grouped by dst
__device__ float g_st1 [NSH * HID_D];  // shape_table @ W1 (row0 = 0)
__device__ float g_ct1 [NCO * HID_D];  // color_table @ W1 (row0 = 0)
__device__ float g_pool[NG * HID_D];
__device__ float g_cnt [NG];

__device__ __forceinline__ void red_v4(float* p, float4 v) {
    asm volatile("red.global.add.v4.f32 [%0], {%1,%2,%3,%4};"
                 :: "l"(p), "f"(v.x), "f"(v.y), "f"(v.z), "f"(v.w) : "memory");
}
__device__ __forceinline__ float4 f4add(float4 a, float4 b) {
    return make_float4(a.x + b.x, a.y + b.y, a.z + b.z, a.w + b.w);
}

// ---------------- CSR build ---------------------------------------------------

__global__ void k_zero() {
    int i = blockIdx.x * blockDim.x + threadIdx.x;
    if (i < NN) g_ideg[i] = 0;
    if (i < NG * HID_D) g_pool[i] = 0.0f;
    if (i < NG) g_cnt[i] = 0.0f;
}

__global__ void k_deg(const int* __restrict__ dst) {
    int e = blockIdx.x * blockDim.x + threadIdx.x;
    if (e < NE) atomicAdd(&g_ideg[dst[e]], 1);
}

// block-local inclusive scan of degrees; block totals to g_bsum
__global__ void k_scan1() {
    __shared__ int s[SCAN_B];
    int i = blockIdx.x * SCAN_B + threadIdx.x;
    int v = (i < NN) ? g_ideg[i] : 0;
    s[threadIdx.x] = v;
    __syncthreads();
    for (int o = 1; o < SCAN_B; o <<= 1) {
        int t = (threadIdx.x >= o) ? s[threadIdx.x - o] : 0;
        __syncthreads();
        s[threadIdx.x] += t;
        __syncthreads();
    }
    if (i < NN) g_off[i] = s[threadIdx.x];
    if (threadIdx.x == SCAN_B - 1) g_bsum[blockIdx.x] = s[SCAN_B - 1];
}

// exclusive scan of the block sums (single block)
__global__ void k_scan2() {
    __shared__ int s[512];
    int t = threadIdx.x;
    int orig = (t < NBLK) ? g_bsum[t] : 0;
    s[t] = orig;
    __syncthreads();
    for (int o = 1; o < 512; o <<= 1) {
        int v = (t >= o) ? s[t - o] : 0;
        __syncthreads();
        s[t] += v;
        __syncthreads();
    }
    if (t < NBLK) g_bsum[t] = s[t] - orig;
    if (t == 0) g_off[NN] = NE;
}

// exclusive global offsets + cursors; also dis = rsqrt(1+deg) and cnt[batch]++
__global__ void k_scan3(const int* __restrict__ batch) {
    int i = blockIdx.x * SCAN_B + threadIdx.x;
    if (i >= NN) return;
    int dg = g_ideg[i];
    int v = g_off[i] - dg + g_bsum[blockIdx.x];
    g_off[i] = v;
    g_cur[i] = v;
    g_dis[i] = rsqrtf(1.0f + (float)dg);
    atomicAdd(&g_cnt[batch[i]], 1.0f);
}

// fill CSR: src ids grouped by dst
__global__ void k_fill(const int* __restrict__ src, const int* __restrict__ dst) {
    int e = blockIdx.x * blockDim.x + threadIdx.x;
    if (e >= NE) return;
    int p = atomicAdd(&g_cur[dst[e]], 1);
    g_csrc[p] = src[e];
}

// ---------------- layer-1 table precompute + hs gather ------------------------

// ST1 = shape_table@W1 (row0=0); CT1 = color_table@W1 (row0=0). One block.
__global__ void k_tab1(const float* __restrict__ stab, const float* __restrict__ ctab,
                       const float* __restrict__ W1) {
    __shared__ float sW[EMB_D * HID_D];   // 8KB
    for (int t = threadIdx.x; t < EMB_D * HID_D; t += blockDim.x) sW[t] = W1[t];
    __syncthreads();
    for (int idx = threadIdx.x; idx < (NSH + NCO) * HID_D; idx += blockDim.x) {
        int row = idx / HID_D, j = idx % HID_D;
        const float* tab;
        float* out;
        int r;
        if (row < NSH) { tab = stab; out = g_st1; r = row; }
        else           { tab = ctab; out = g_ct1; r = row - NSH; }
        float s = 0.0f;
        if (r != 0) {   // padding row stays zero
#pragma unroll
            for (int k = 0; k < EMB_D; k++)
                s = fmaf(tab[r * EMB_D + k], sW[k * HID_D + j], s);
        }
        out[(r)*HID_D + j] = s;
    }
}

// hs1[i] = (ST1[sid[i]] + CT1[cid[i]]) * dis[i]   -> g_h   (write-bound)
__global__ void k_hs1(const int* __restrict__ sid, const int* __restrict__ cid) {
    int t = blockIdx.x * blockDim.x + threadIdx.x;
    if (t >= NN * 16) return;
    int i = t >> 4, jq = t & 15;
    int s = __ldg(sid + i), c = __ldg(cid + i);
    float d = g_dis[i];
    float4 sv = ((const float4*)g_st1)[s * 16 + jq];
    float4 cv = ((const float4*)g_ct1)[c * 16 + jq];
    ((float4*)g_h)[t] = make_float4((sv.x + cv.x) * d, (sv.y + cv.y) * d,
                                    (sv.z + cv.z) * d, (sv.w + cv.w) * d);
}

// ---------------- mm2: hs = (g_a @ W2) * dis -> g_h --------------------------
__global__ void k_mm2(const float* __restrict__ W2) {
    __shared__ float4 sW[HID_D * 16];          // 4KB
    __shared__ float  sx[16 * HID_D];          // 4KB
    int tid = threadIdx.x;
    int node0 = blockIdx.x * 16;
#pragma unroll
    for (int t = tid; t < HID_D * 16; t += 256) sW[t] = ((const float4*)W2)[t];
    ((float4*)sx)[tid] = ((const float4*)(g_a + (long)node0 * HID_D))[tid];
    __syncthreads();
    int n = tid >> 4, jq = tid & 15;
    int i = node0 + n;
    float4 acc = make_float4(0, 0, 0, 0);
#pragma unroll
    for (int k = 0; k < HID_D; k++) {
        float xk = sx[n * HID_D + k];
        float4 w = sW[k * 16 + jq];
        acc.x = fmaf(xk, w.x, acc.x);
        acc.y = fmaf(xk, w.y, acc.y);
        acc.z = fmaf(xk, w.z, acc.z);
        acc.w = fmaf(xk, w.w, acc.w);
    }
    float d = g_dis[i];
    ((float4*)g_h)[i * 16 + jq] = make_float4(acc.x * d, acc.y * d, acc.z * d, acc.w * d);
}

// ---------------- CSR gather + fused epilogues -------------------------------
// acc = hs_i + sum_{s in in(i)} hs_s ; out_i = relu(dis_i * acc + bias)

__device__ __forceinline__ float4 gather_acc(int i, int jq) {
    int beg = g_off[i], end = g_off[i + 1];
    float4 acc = ((const float4*)g_h)[i * 16 + jq];   // self-loop seed
    int e = beg;
    for (; e + 4 <= end; e += 4) {                    // 4-way MLP
        int s0 = __ldg(g_csrc + e + 0);
        int s1 = __ldg(g_csrc + e + 1);
        int s2 = __ldg(g_csrc + e + 2);
        int s3 = __ldg(g_csrc + e + 3);
        float4 v0 = ((const float4*)g_h)[s0 * 16 + jq];
        float4 v1 = ((const float4*)g_h)[s1 * 16 + jq];
        float4 v2 = ((const float4*)g_h)[s2 * 16 + jq];
        float4 v3 = ((const float4*)g_h)[s3 * 16 + jq];
        acc = f4add(acc, f4add(f4add(v0, v1), f4add(v2, v3)));
    }
    for (; e < end; e++) {
        int s = __ldg(g_csrc + e);
        acc = f4add(acc, ((const float4*)g_h)[s * 16 + jq]);
    }
    return acc;
}

__global__ void k_gather1(const float* __restrict__ bias) {
    int t = blockIdx.x * blockDim.x + threadIdx.x;
    if (t >= NN * 16) return;
    int i = t >> 4, jq = t & 15;
    float4 acc = gather_acc(i, jq);
    float d = g_dis[i];
    float4 b = ((const float4*)bias)[jq];
    float4 v;
    v.x = fmaxf(fmaf(d, acc.x, b.x), 0.0f);
    v.y = fmaxf(fmaf(d, acc.y, b.y), 0.0f);
    v.z = fmaxf(fmaf(d, acc.z, b.z), 0.0f);
    v.w = fmaxf(fmaf(d, acc.w, b.w), 0.0f);
    ((float4*)g_a)[t] = v;
}

__global__ void k_gather2(const float* __restrict__ bias, const int* __restrict__ batch) {
    int t = blockIdx.x * blockDim.x + threadIdx.x;
    if (t >= NN * 16) return;
    int i = t >> 4, jq = t & 15;
    float4 acc = gather_acc(i, jq);
    float d = g_dis[i];
    float4 b = ((const float4*)bias)[jq];
    float4 v;
    v.x = fmaxf(fmaf(d, acc.x, b.x), 0.0f);
    v.y = fmaxf(fmaf(d, acc.y, b.y), 0.0f);
    v.z = fmaxf(fmaf(d, acc.z, b.z), 0.0f);
    v.w = fmaxf(fmaf(d, acc.w, b.w), 0.0f);
    int bt = __ldg(batch + i);
    red_v4(g_pool + bt * HID_D + jq * 4, v);
}

// out[b,c] = bl[c] + sum_j pool[b,j]/cnt[b] * Wl[j,c]
__global__ void k_final(const float* __restrict__ Wl, const float* __restrict__ bl,
                        float* __restrict__ out) {
    int idx = blockIdx.x * blockDim.x + threadIdx.x;
    if (idx >= NG * NC) return;
    int b = idx / NC, c = idx % NC;
    float inv = 1.0f / fmaxf(g_cnt[b], 1.0f);
    float s = bl[c];
#pragma unroll
    for (int j = 0; j < HID_D; j++)
        s = fmaf(g_pool[b * HID_D + j] * inv, Wl[j * NC + c], s);
    out[idx] = s;
}

// ---------------- launch ------------------------------------------------------
extern "C" void kernel_launch(void* const* d_in, const int* in_sizes, int n_in,
                              void* d_out, int out_size) {
    const int*   shape_id = (const int*)  d_in[0];
    const int*   color_id = (const int*)  d_in[1];
    const int*   edge     = (const int*)  d_in[2];   // [2, NE]
    const int*   batch    = (const int*)  d_in[3];
    const float* stab     = (const float*)d_in[4];
    const float* ctab     = (const float*)d_in[5];
    const float* W1       = (const float*)d_in[6];
    const float* b1       = (const float*)d_in[7];
    const float* W2       = (const float*)d_in[8];
    const float* b2       = (const float*)d_in[9];
    const float* Wl       = (const float*)d_in[10];
    const float* bl       = (const float*)d_in[11];
    float*       out      = (float*)d_out;

    const int* src = edge;
    const int* dst = edge + NE;

    const int T = 256;
    auto blk = [](long n, int t) { return (int)((n + t - 1) / t); };

    // CSR build + norm precompute
    k_zero <<<blk(NN, T), T>>>();
    k_tab1 <<<1, 256>>>(stab, ctab, W1);       // independent of everything above
    k_deg  <<<blk(NE, T), T>>>(dst);
    k_scan1<<<NBLK, SCAN_B>>>();
    k_scan2<<<1, 512>>>();
    k_scan3<<<NBLK, SCAN_B>>>(batch);
    k_fill <<<blk(NE, T), T>>>(src, dst);

    // layer 1 (matmul collapsed into table lookup)
    k_hs1    <<<blk((long)NN * 16, T), T>>>(shape_id, color_id);
    k_gather1<<<blk((long)NN * 16, T), T>>>(b1);

    // layer 2
    k_mm2    <<<NN / 16, T>>>(W2);
    k_gather2<<<blk((long)NN * 16, T), T>>>(b2, batch);

    k_final<<<blk(NG * NC, T), T>>>(Wl, bl, out);
}